// round 1
// baseline (speedup 1.0000x reference)
#include <cuda_runtime.h>

// Problem constants
#define NRED   100000      // reduction length (C*RF*LEN = 1*50*2000)
#define TT     32          // timesteps
#define KFEAT  512         // out features
#define THRESH 10.0f
#define KWTA   16

// GEMM tiling
#define SPLITS 73
#define KB     32                 // k-indices per smem tile
#define NTILES 43                 // 43*32 = 1376 >= ceil(100000/73)
#define CHUNK  (NTILES * KB)      // 1376
#define MTILE  256
#define SMEM_FLOATS (2*KB*MTILE + 2*KB*TT)   // 18432 floats = 73728 B

// Device scratch (no dynamic allocation allowed)
__device__ float g_partial[SPLITS * KFEAT * TT];   // ~4.85 MB
__device__ float g_dot[KFEAT * TT];

typedef unsigned long long ull;

__device__ __forceinline__ ull pack2(float lo, float hi) {
    ull r; asm("mov.b64 %0, {%1, %2};" : "=l"(r) : "f"(lo), "f"(hi)); return r;
}
__device__ __forceinline__ void ffma2(ull& d, ull a, ull b) {
    asm("fma.rn.f32x2 %0, %1, %2, %0;" : "+l"(d) : "l"(a), "l"(b));
}
__device__ __forceinline__ float2 unpack2(ull v) {
    float2 f; asm("mov.b64 {%0, %1}, %2;" : "=f"(f.x), "=f"(f.y) : "l"(v)); return f;
}

// ---------------------------------------------------------------------------
// GEMM: partial[s][k][t] = sum over k-chunk of W[k][i] * R[t][i]
// grid (73 splits, 2 m-tiles), 256 threads
// ---------------------------------------------------------------------------
__global__ void __launch_bounds__(256, 1)
gemm_kernel(const float* __restrict__ W, const float* __restrict__ R) {
    extern __shared__ float smem[];
    float* w_s = smem;                 // [2][KB][MTILE], layout w_s[buf][k][m]
    float* r_s = smem + 2 * KB * MTILE; // [2][KB][TT],   layout r_s[buf][k][t]

    const int tid   = threadIdx.x;
    const int split = blockIdx.x;
    const int mt    = blockIdx.y;
    const int kbase = split * CHUNK;
    const int m0    = mt * MTILE;

    // loader mapping: warp spans 32 distinct rows -> conflict-free transposed STS
    const int lr = tid & 31;   // row (feature) / t
    const int lc = tid >> 5;   // col4 group (0..7), 8 warps each with fixed lc

    // compute mapping: tx over t (8 groups x 4 t), ty over features (32 x 8)
    const int tx = tid & 7;
    const int ty = tid >> 3;

    ull acc[4][4];
#pragma unroll
    for (int p = 0; p < 4; p++)
#pragma unroll
        for (int j = 0; j < 4; j++) acc[p][j] = 0ull;

    float4 wreg[8];
    float4 rreg;

    // ---- prologue: load tile 0 ----
    {
        const int kp = kbase + 0 * KB + lc * 4;
        const bool ok = kp < NRED;
#pragma unroll
        for (int it = 0; it < 8; it++) {
            wreg[it] = ok ? *(const float4*)(W + (size_t)(m0 + lr + 32 * it) * NRED + kp)
                          : make_float4(0.f, 0.f, 0.f, 0.f);
        }
        rreg = ok ? *(const float4*)(R + (size_t)lr * NRED + kp)
                  : make_float4(0.f, 0.f, 0.f, 0.f);
    }
    {
        float* wb = w_s;  // buf 0
        float* rb = r_s;
#pragma unroll
        for (int it = 0; it < 8; it++) {
            const int row = lr + 32 * it;
            wb[(lc * 4 + 0) * MTILE + row] = wreg[it].x;
            wb[(lc * 4 + 1) * MTILE + row] = wreg[it].y;
            wb[(lc * 4 + 2) * MTILE + row] = wreg[it].z;
            wb[(lc * 4 + 3) * MTILE + row] = wreg[it].w;
        }
        rb[(lc * 4 + 0) * TT + lr] = rreg.x;
        rb[(lc * 4 + 1) * TT + lr] = rreg.y;
        rb[(lc * 4 + 2) * TT + lr] = rreg.z;
        rb[(lc * 4 + 3) * TT + lr] = rreg.w;
    }
    __syncthreads();

    for (int tl = 0; tl < NTILES; tl++) {
        // prefetch next tile into registers (latency hidden by compute below)
        if (tl + 1 < NTILES) {
            const int kp = kbase + (tl + 1) * KB + lc * 4;
            const bool ok = kp < NRED;
#pragma unroll
            for (int it = 0; it < 8; it++) {
                wreg[it] = ok ? *(const float4*)(W + (size_t)(m0 + lr + 32 * it) * NRED + kp)
                              : make_float4(0.f, 0.f, 0.f, 0.f);
            }
            rreg = ok ? *(const float4*)(R + (size_t)lr * NRED + kp)
                      : make_float4(0.f, 0.f, 0.f, 0.f);
        }

        // compute current tile
        {
            const int buf = tl & 1;
            const float* wb = w_s + buf * KB * MTILE + ty * 8;
            const float* rb = r_s + buf * KB * TT + tx * 4;
#pragma unroll
            for (int kk = 0; kk < KB; kk++) {
                // features ty*8 .. ty*8+7 as pre-packed f32x2 pairs (zero-cost)
                ulonglong2 wa = *(const ulonglong2*)(wb + kk * MTILE);
                ulonglong2 wc = *(const ulonglong2*)(wb + kk * MTILE + 4);
                float4     rr = *(const float4*)(rb + kk * TT);
                ull b0 = pack2(rr.x, rr.x);
                ull b1 = pack2(rr.y, rr.y);
                ull b2 = pack2(rr.z, rr.z);
                ull b3 = pack2(rr.w, rr.w);
                ffma2(acc[0][0], wa.x, b0); ffma2(acc[0][1], wa.x, b1);
                ffma2(acc[0][2], wa.x, b2); ffma2(acc[0][3], wa.x, b3);
                ffma2(acc[1][0], wa.y, b0); ffma2(acc[1][1], wa.y, b1);
                ffma2(acc[1][2], wa.y, b2); ffma2(acc[1][3], wa.y, b3);
                ffma2(acc[2][0], wc.x, b0); ffma2(acc[2][1], wc.x, b1);
                ffma2(acc[2][2], wc.x, b2); ffma2(acc[2][3], wc.x, b3);
                ffma2(acc[3][0], wc.y, b0); ffma2(acc[3][1], wc.y, b1);
                ffma2(acc[3][2], wc.y, b2); ffma2(acc[3][3], wc.y, b3);
            }
        }

        // stage next tile to the other smem buffer
        if (tl + 1 < NTILES) {
            const int buf = (tl + 1) & 1;
            float* wb = w_s + buf * KB * MTILE;
            float* rb = r_s + buf * KB * TT;
#pragma unroll
            for (int it = 0; it < 8; it++) {
                const int row = lr + 32 * it;
                wb[(lc * 4 + 0) * MTILE + row] = wreg[it].x;
                wb[(lc * 4 + 1) * MTILE + row] = wreg[it].y;
                wb[(lc * 4 + 2) * MTILE + row] = wreg[it].z;
                wb[(lc * 4 + 3) * MTILE + row] = wreg[it].w;
            }
            rb[(lc * 4 + 0) * TT + lr] = rreg.x;
            rb[(lc * 4 + 1) * TT + lr] = rreg.y;
            rb[(lc * 4 + 2) * TT + lr] = rreg.z;
            rb[(lc * 4 + 3) * TT + lr] = rreg.w;
            __syncthreads();
        }
    }

    // write partials: feature = m0 + ty*8 + 2p(+1), t = tx*4 + j
    float* pb = g_partial + ((size_t)split * KFEAT + m0 + ty * 8) * TT + tx * 4;
#pragma unroll
    for (int p = 0; p < 4; p++) {
#pragma unroll
        for (int j = 0; j < 4; j++) {
            float2 f = unpack2(acc[p][j]);
            pb[(2 * p + 0) * TT + j] = f.x;
            pb[(2 * p + 1) * TT + j] = f.y;
        }
    }
}

// ---------------------------------------------------------------------------
// Reduce partials across splits: g_dot[k*TT+t] = sum_s g_partial[s][k][t]
// ---------------------------------------------------------------------------
__global__ void __launch_bounds__(256)
reduce_kernel() {
    const int j = blockIdx.x * 256 + threadIdx.x;   // < KFEAT*TT = 16384
    float s = 0.0f;
#pragma unroll 8
    for (int sp = 0; sp < SPLITS; sp++) s += g_partial[sp * (KFEAT * TT) + j];
    g_dot[j] = s;
}

// ---------------------------------------------------------------------------
// Winner selection (exact replication of reference math), 1 block x 512 threads
// ---------------------------------------------------------------------------
__global__ void __launch_bounds__(512, 1)
winner_kernel(float* __restrict__ out) {
    __shared__ float tot_s[KFEAT];
    __shared__ float red_s[16];
    __shared__ float v_s;

    const int k = threadIdx.x;

    float pot[TT];
    int nspk = 0;
#pragma unroll
    for (int t = 0; t < TT; t++) {
        float d = g_dot[k * TT + t];
        float p = (d > THRESH) ? d : 0.0f;
        pot[t] = p;
        nspk += (p > 0.0f) ? 1 : 0;
    }
    // first = clip(T - nspk, 0, T-1); nspk in [0,32] so only upper clip matters
    int first = TT - nspk;
    if (first > TT - 1) first = TT - 1;
    if (first < 0) first = 0;
    // value = pot[first][k] (recompute from g_dot to keep pot[] in registers)
    float dv = g_dot[k * TT + first];
    float value = (dv > THRESH) ? dv : 0.0f;
    float sval = (nspk > 0) ? value : 0.0f;

    // v = max_k(value * sign(nspk)) * T   — block max reduction
    float m = sval;
#pragma unroll
    for (int o = 16; o > 0; o >>= 1)
        m = fmaxf(m, __shfl_xor_sync(0xffffffffu, m, o));
    if ((k & 31) == 0) red_s[k >> 5] = m;
    __syncthreads();
    if (k == 0) {
        float mm = red_s[0];
#pragma unroll
        for (int i = 1; i < 16; i++) mm = fmaxf(mm, red_s[i]);
        v_s = mm * (float)TT;
    }
    __syncthreads();
    const float v = v_s;

    const float fns = (float)nspk;
    const float total = fns * value + fns * v;   // == truncated_pot.sum(dim=0)
    tot_s[k] = total;
    __syncthreads();

    // Rank-count == sequential suppressive argmax with first-index tie-break:
    // winner iff total > 0 and fewer than KWTA elements strictly ahead.
    int cnt = 0;
    const float4* t4 = (const float4*)tot_s;
#pragma unroll 8
    for (int jj = 0; jj < KFEAT / 4; jj++) {
        float4 tv = t4[jj];
        const int j0 = jj * 4;
        cnt += ((tv.x > total) || (tv.x == total && (j0 + 0) < k)) ? 1 : 0;
        cnt += ((tv.y > total) || (tv.y == total && (j0 + 1) < k)) ? 1 : 0;
        cnt += ((tv.z > total) || (tv.z == total && (j0 + 2) < k)) ? 1 : 0;
        cnt += ((tv.w > total) || (tv.w == total && (j0 + 3) < k)) ? 1 : 0;
    }
    const bool win = (total > 0.0f) && (cnt < KWTA);

#pragma unroll
    for (int t = 0; t < TT; t++)
        out[t * KFEAT + k] = (win && pot[t] > 0.0f) ? 1.0f : 0.0f;
}

// ---------------------------------------------------------------------------
extern "C" void kernel_launch(void* const* d_in, const int* in_sizes, int n_in,
                              void* d_out, int out_size) {
    const float* a = (const float*)d_in[0];
    const float* b = (const float*)d_in[1];
    // rec_field has 32*100000 elems, weight 512*100000; disambiguate by size
    const float* rec = a;
    const float* wgt = b;
    if (in_sizes[0] > in_sizes[1]) { rec = b; wgt = a; }

    const int smem_bytes = SMEM_FLOATS * (int)sizeof(float);  // 73728
    cudaFuncSetAttribute(gemm_kernel,
                         cudaFuncAttributeMaxDynamicSharedMemorySize, smem_bytes);

    dim3 grid(SPLITS, 2);
    gemm_kernel<<<grid, 256, smem_bytes>>>(wgt, rec);
    reduce_kernel<<<(KFEAT * TT) / 256, 256>>>();
    winner_kernel<<<1, 512>>>((float*)d_out);
}